// round 5
// baseline (speedup 1.0000x reference)
#include <cuda_runtime.h>
#include <cstdint>

#define D 8192
#define THREADS 512
#define NWARPS (THREADS / 32)           // 16
#define BUF 1024                        // candidate buffer (floats)
#define ROW_BYTES (D * 4)               // 32768
#define NSTAGE 3                        // SMEM ring stages (depth-2 prefetch)

// ---- PTX helpers (sm_90+/sm_103a) ----
__device__ __forceinline__ uint32_t smem_u32(const void* p) {
    return (uint32_t)__cvta_generic_to_shared(p);
}
__device__ __forceinline__ void mbar_init(uint32_t mbar, uint32_t count) {
    asm volatile("mbarrier.init.shared::cta.b64 [%0], %1;" :: "r"(mbar), "r"(count) : "memory");
}
__device__ __forceinline__ void mbar_expect_tx(uint32_t mbar, uint32_t bytes) {
    asm volatile("mbarrier.arrive.expect_tx.shared::cta.b64 _, [%0], %1;"
                 :: "r"(mbar), "r"(bytes) : "memory");
}
__device__ __forceinline__ void tma_1d_g2s(uint32_t dst_smem, const void* src_gmem,
                                           uint32_t bytes, uint32_t mbar) {
    asm volatile("cp.async.bulk.shared::cluster.global.mbarrier::complete_tx::bytes "
                 "[%0], [%1], %2, [%3];"
                 :: "r"(dst_smem), "l"(src_gmem), "r"(bytes), "r"(mbar) : "memory");
}
__device__ __forceinline__ void mbar_wait(uint32_t mbar, uint32_t parity) {
    uint32_t done;
    asm volatile("{\n\t.reg .pred p;\n\t"
                 "mbarrier.try_wait.parity.acquire.cta.shared::cta.b64 p, [%1], %2;\n\t"
                 "selp.b32 %0, 1, 0, p;\n\t}"
                 : "=r"(done) : "r"(mbar), "r"(parity) : "memory");
    if (!done) {
        asm volatile("{\n\t.reg .pred P1;\n"
                     "WL_%=:\n\t"
                     "mbarrier.try_wait.parity.acquire.cta.shared::cta.b64 P1, [%0], %1, 0x989680;\n\t"
                     "@P1 bra.uni WD_%=;\n\t"
                     "bra.uni WL_%=;\n"
                     "WD_%=:\n\t}"
                     :: "r"(mbar), "r"(parity) : "memory");
    }
}

extern __shared__ float srow[];          // dynamic: NSTAGE * D floats = 96 KB ring

__global__ __launch_bounds__(THREADS, 2)
void sparsemax_kernel(const float* __restrict__ x, float* __restrict__ out, int nrows) {
    __shared__ float sbuf[BUF];          // candidates > max-1
    __shared__ float swarp[NWARPS];      // block max scratch
    __shared__ float sredf[NWARPS];      // fallback sum scratch
    __shared__ int   sredk[NWARPS];      // fallback count scratch
    __shared__ int   s_cnt;
    __shared__ float s_tau;
    __shared__ int   s_k;
    __shared__ __align__(8) uint64_t mbar_storage[NSTAGE];

    const int tid = threadIdx.x;
    const int lid = tid & 31;
    const int stride = gridDim.x;
    int r = blockIdx.x;
    if (r >= nrows) return;

    uint32_t mb[NSTAGE], ba[NSTAGE];
    #pragma unroll
    for (int j = 0; j < NSTAGE; j++) {
        mb[j] = smem_u32(&mbar_storage[j]);
        ba[j] = smem_u32(&srow[(size_t)j * D]);
    }

    if (tid == 0) {
        #pragma unroll
        for (int j = 0; j < NSTAGE; j++) mbar_init(mb[j], 1);
        s_cnt = 0;
        asm volatile("fence.mbarrier_init.release.cluster;" ::: "memory");
    }
    __syncthreads();

    // ---- prologue: issue TMA for rows r, r+stride into stages 0,1 ----
    if (tid == 0) {
        #pragma unroll
        for (int j = 0; j < 2; j++) {
            long long rj = (long long)r + (long long)j * stride;
            if (rj < nrows) {
                mbar_expect_tx(mb[j], ROW_BYTES);
                tma_1d_g2s(ba[j], x + (size_t)rj * D, ROW_BYTES, mb[j]);
            }
        }
    }

    int b = 0;                 // current ring slot
    uint32_t ph = 0u;          // per-slot parity bits

    while (true) {
        // ---- keep depth-2: issue TMA for row r+2*stride into slot (b+2)%3 ----
        {
            long long r2 = (long long)r + 2LL * stride;
            if (tid == 0 && r2 < nrows) {
                int b2 = b + 2; if (b2 >= NSTAGE) b2 -= NSTAGE;
                mbar_expect_tx(mb[b2], ROW_BYTES);
                tma_1d_g2s(ba[b2], x + (size_t)r2 * D, ROW_BYTES, mb[b2]);
            }
        }

        // ---- wait for current stage, consume into registers ----
        mbar_wait(mb[b], (ph >> b) & 1u);
        ph ^= (1u << b);

        const float4* sp = reinterpret_cast<const float4*>(srow + (size_t)b * D);
        float4 c0 = sp[tid];
        float4 c1 = sp[tid + THREADS];
        float4 c2 = sp[tid + 2 * THREADS];
        float4 c3 = sp[tid + 3 * THREADS];
        // NOTE: no barrier needed here — slot b is reissued only at the top of the
        // NEXT iteration, and >=2 __syncthreads separate every thread's consume
        // from that reissue.

        // ---- max reduction ----
        float m = fmaxf(fmaxf(fmaxf(c0.x, c0.y), fmaxf(c0.z, c0.w)),
                        fmaxf(fmaxf(c1.x, c1.y), fmaxf(c1.z, c1.w)));
        m = fmaxf(m, fmaxf(fmaxf(c2.x, c2.y), fmaxf(c2.z, c2.w)));
        m = fmaxf(m, fmaxf(fmaxf(c3.x, c3.y), fmaxf(c3.z, c3.w)));
        #pragma unroll
        for (int o = 16; o > 0; o >>= 1)
            m = fmaxf(m, __shfl_xor_sync(0xffffffffu, m, o));
        if (lid == 0) swarp[tid >> 5] = m;
        __syncthreads();

        float mm = swarp[lid & (NWARPS - 1)];
        #pragma unroll
        for (int o = NWARPS / 2; o > 0; o >>= 1)
            mm = fmaxf(mm, __shfl_xor_sync(0xffffffffu, mm, o));
        const float thr = mm - 1.0f;     // valid lower bound on tau*

        // ---- gather candidates {x > thr} (rare for gaussian rows) ----
        {
            float vals[16] = {c0.x, c0.y, c0.z, c0.w, c1.x, c1.y, c1.z, c1.w,
                              c2.x, c2.y, c2.z, c2.w, c3.x, c3.y, c3.z, c3.w};
            #pragma unroll
            for (int i = 0; i < 16; i++) {
                if (vals[i] > thr) {
                    int p = atomicAdd(&s_cnt, 1);
                    if (p < BUF) sbuf[p] = vals[i];
                }
            }
        }
        __syncthreads();
        const int cnt = s_cnt;

        if (cnt <= BUF) {
            // ---- Michelot fixed-point on the tiny candidate set (warp 0) ----
            if (tid < 32) {
                float tau = thr;
                int prev = -1;
                for (int it = 0; it < cnt + 2; it++) {
                    float s = 0.0f; int k = 0;
                    for (int j = tid; j < cnt; j += 32) {
                        float v = sbuf[j];
                        if (v > tau) { s += v; k++; }
                    }
                    #pragma unroll
                    for (int o = 16; o > 0; o >>= 1) {
                        s += __shfl_xor_sync(0xffffffffu, s, o);
                        k += __shfl_xor_sync(0xffffffffu, k, o);
                    }
                    tau = (s - 1.0f) / (float)k;
                    if (k == prev) break;   // active set stable -> fixed point
                    prev = k;
                }
                if (tid == 0) s_tau = tau;
            }
            __syncthreads();
        } else {
            // ---- Fallback: block-wide Michelot over register values ----
            float tau = thr;
            int prev = -1;
            for (int it = 0; it < D + 2; it++) {
                float s = 0.0f; int k = 0;
                float vals[16] = {c0.x, c0.y, c0.z, c0.w, c1.x, c1.y, c1.z, c1.w,
                                  c2.x, c2.y, c2.z, c2.w, c3.x, c3.y, c3.z, c3.w};
                #pragma unroll
                for (int i = 0; i < 16; i++)
                    if (vals[i] > tau) { s += vals[i]; k++; }
                #pragma unroll
                for (int o = 16; o > 0; o >>= 1) {
                    s += __shfl_xor_sync(0xffffffffu, s, o);
                    k += __shfl_xor_sync(0xffffffffu, k, o);
                }
                if (lid == 0) { sredf[tid >> 5] = s; sredk[tid >> 5] = k; }
                __syncthreads();
                if (tid == 0) {
                    float S = 0.0f; int K = 0;
                    #pragma unroll
                    for (int w = 0; w < NWARPS; w++) { S += sredf[w]; K += sredk[w]; }
                    s_tau = (S - 1.0f) / (float)K;
                    s_k = K;
                }
                __syncthreads();
                tau = s_tau;
                int K = s_k;
                if (K == prev) break;
                prev = K;
            }
            __syncthreads();
        }

        if (tid == 0) s_cnt = 0;   // safe: next gather is >=2 barriers away

        // ---- write relu(x - tau) from registers (streaming stores) ----
        const float tau = s_tau;
        c0.x = fmaxf(c0.x - tau, 0.0f); c0.y = fmaxf(c0.y - tau, 0.0f);
        c0.z = fmaxf(c0.z - tau, 0.0f); c0.w = fmaxf(c0.w - tau, 0.0f);
        c1.x = fmaxf(c1.x - tau, 0.0f); c1.y = fmaxf(c1.y - tau, 0.0f);
        c1.z = fmaxf(c1.z - tau, 0.0f); c1.w = fmaxf(c1.w - tau, 0.0f);
        c2.x = fmaxf(c2.x - tau, 0.0f); c2.y = fmaxf(c2.y - tau, 0.0f);
        c2.z = fmaxf(c2.z - tau, 0.0f); c2.w = fmaxf(c2.w - tau, 0.0f);
        c3.x = fmaxf(c3.x - tau, 0.0f); c3.y = fmaxf(c3.y - tau, 0.0f);
        c3.z = fmaxf(c3.z - tau, 0.0f); c3.w = fmaxf(c3.w - tau, 0.0f);
        float4* __restrict__ xout = reinterpret_cast<float4*>(out + (size_t)r * D);
        __stcs(&xout[tid],               c0);
        __stcs(&xout[tid + THREADS],     c1);
        __stcs(&xout[tid + 2 * THREADS], c2);
        __stcs(&xout[tid + 3 * THREADS], c3);

        r += stride;
        if (r >= nrows) break;
        b = (b == NSTAGE - 1) ? 0 : b + 1;
    }
}

extern "C" void kernel_launch(void* const* d_in, const int* in_sizes, int n_in,
                              void* d_out, int out_size) {
    const float* x = (const float*)d_in[0];
    float* out = (float*)d_out;
    const int rows = in_sizes[0] / D;   // 8192

    const int dyn_smem = NSTAGE * D * (int)sizeof(float);   // 96 KB ring
    cudaFuncSetAttribute(sparsemax_kernel,
                         cudaFuncAttributeMaxDynamicSharedMemorySize, dyn_smem);

    int dev = 0;
    cudaGetDevice(&dev);
    int nsm = 148;
    cudaDeviceGetAttribute(&nsm, cudaDevAttrMultiProcessorCount, dev);
    int grid = nsm * 2;                 // 2 CTAs/SM, persistent, depth-2 TMA pipeline
    if (grid > rows) grid = rows;

    sparsemax_kernel<<<grid, THREADS, dyn_smem>>>(x, out, rows);
}

// round 6
// speedup vs baseline: 1.2698x; 1.2698x over previous
#include <cuda_runtime.h>
#include <cstdint>

#define D 8192
#define THREADS 512
#define NWARPS (THREADS / 32)           // 16
#define BUF 1024                        // candidate buffer (floats)
#define ROW_BYTES (D * 4)               // 32768

// ---- PTX helpers (sm_90+/sm_103a) ----
__device__ __forceinline__ uint32_t smem_u32(const void* p) {
    return (uint32_t)__cvta_generic_to_shared(p);
}
__device__ __forceinline__ void mbar_init(uint32_t mbar, uint32_t count) {
    asm volatile("mbarrier.init.shared::cta.b64 [%0], %1;" :: "r"(mbar), "r"(count) : "memory");
}
__device__ __forceinline__ void mbar_expect_tx(uint32_t mbar, uint32_t bytes) {
    asm volatile("mbarrier.arrive.expect_tx.shared::cta.b64 _, [%0], %1;"
                 :: "r"(mbar), "r"(bytes) : "memory");
}
__device__ __forceinline__ void tma_1d_g2s(uint32_t dst_smem, const void* src_gmem,
                                           uint32_t bytes, uint32_t mbar) {
    asm volatile("cp.async.bulk.shared::cluster.global.mbarrier::complete_tx::bytes "
                 "[%0], [%1], %2, [%3];"
                 :: "r"(dst_smem), "l"(src_gmem), "r"(bytes), "r"(mbar) : "memory");
}
__device__ __forceinline__ void l2_prefetch_bulk(const void* src_gmem, uint32_t bytes) {
    asm volatile("cp.async.bulk.prefetch.L2.global [%0], %1;"
                 :: "l"(src_gmem), "r"(bytes) : "memory");
}
__device__ __forceinline__ void mbar_wait(uint32_t mbar, uint32_t parity) {
    uint32_t done;
    asm volatile("{\n\t.reg .pred p;\n\t"
                 "mbarrier.try_wait.parity.acquire.cta.shared::cta.b64 p, [%1], %2;\n\t"
                 "selp.b32 %0, 1, 0, p;\n\t}"
                 : "=r"(done) : "r"(mbar), "r"(parity) : "memory");
    if (!done) {
        asm volatile("{\n\t.reg .pred P1;\n"
                     "WL_%=:\n\t"
                     "mbarrier.try_wait.parity.acquire.cta.shared::cta.b64 P1, [%0], %1, 0x989680;\n\t"
                     "@P1 bra.uni WD_%=;\n\t"
                     "bra.uni WL_%=;\n"
                     "WD_%=:\n\t}"
                     :: "r"(mbar), "r"(parity) : "memory");
    }
}

extern __shared__ float srow[];          // dynamic: 2 * D floats = 64 KB (double buffer)

__global__ __launch_bounds__(THREADS, 3)
void sparsemax_kernel(const float* __restrict__ x, float* __restrict__ out, int nrows) {
    __shared__ float sbuf[BUF];          // candidates > max-1
    __shared__ float swarp[NWARPS];      // block max scratch
    __shared__ float sredf[NWARPS];      // fallback sum scratch
    __shared__ int   sredk[NWARPS];      // fallback count scratch
    __shared__ int   s_cnt;
    __shared__ float s_tau;
    __shared__ int   s_k;
    __shared__ __align__(8) uint64_t mbar_storage[2];

    const int tid = threadIdx.x;
    const int lid = tid & 31;
    const int stride = gridDim.x;
    int r = blockIdx.x;
    if (r >= nrows) return;

    const uint32_t mb0 = smem_u32(&mbar_storage[0]);
    const uint32_t mb1 = smem_u32(&mbar_storage[1]);
    const uint32_t ba0 = smem_u32(&srow[0]);
    const uint32_t ba1 = smem_u32(&srow[D]);

    if (tid == 0) {
        mbar_init(mb0, 1);
        mbar_init(mb1, 1);
        s_cnt = 0;
        asm volatile("fence.mbarrier_init.release.cluster;" ::: "memory");
    }
    __syncthreads();

    // ---- prologue: TMA row r into buffer 0; L2-prefetch row r+stride ----
    if (tid == 0) {
        mbar_expect_tx(mb0, ROW_BYTES);
        tma_1d_g2s(ba0, x + (size_t)r * D, ROW_BYTES, mb0);
        long long r1 = (long long)r + stride;
        if (r1 < nrows) l2_prefetch_bulk(x + (size_t)r1 * D, ROW_BYTES);
    }

    int cur = 0;
    uint32_t ph0 = 0u, ph1 = 0u;

    while (true) {
        const int rn = r + stride;
        const bool has_next = (rn < nrows);

        // ---- issue TMA for next row (likely L2-hit) + L2 prefetch 2 rows ahead ----
        if (tid == 0) {
            if (has_next) {
                const uint32_t mbn = (cur == 0) ? mb1 : mb0;
                const uint32_t ban = (cur == 0) ? ba1 : ba0;
                mbar_expect_tx(mbn, ROW_BYTES);
                tma_1d_g2s(ban, x + (size_t)rn * D, ROW_BYTES, mbn);
            }
            long long r2 = (long long)r + 2LL * stride;
            if (r2 < nrows) l2_prefetch_bulk(x + (size_t)r2 * D, ROW_BYTES);
        }

        // ---- wait for current buffer, consume into registers ----
        if (cur == 0) { mbar_wait(mb0, ph0); ph0 ^= 1u; }
        else          { mbar_wait(mb1, ph1); ph1 ^= 1u; }

        const float4* sp = reinterpret_cast<const float4*>(srow + (size_t)cur * D);
        float4 c0 = sp[tid];
        float4 c1 = sp[tid + THREADS];
        float4 c2 = sp[tid + 2 * THREADS];
        float4 c3 = sp[tid + 3 * THREADS];
        __syncthreads();   // all threads done reading buf[cur] -> free for next issue

        // ---- max reduction ----
        float m = fmaxf(fmaxf(fmaxf(c0.x, c0.y), fmaxf(c0.z, c0.w)),
                        fmaxf(fmaxf(c1.x, c1.y), fmaxf(c1.z, c1.w)));
        m = fmaxf(m, fmaxf(fmaxf(c2.x, c2.y), fmaxf(c2.z, c2.w)));
        m = fmaxf(m, fmaxf(fmaxf(c3.x, c3.y), fmaxf(c3.z, c3.w)));
        #pragma unroll
        for (int o = 16; o > 0; o >>= 1)
            m = fmaxf(m, __shfl_xor_sync(0xffffffffu, m, o));
        if (lid == 0) swarp[tid >> 5] = m;
        __syncthreads();

        float mm = swarp[lid & (NWARPS - 1)];
        #pragma unroll
        for (int o = NWARPS / 2; o > 0; o >>= 1)
            mm = fmaxf(mm, __shfl_xor_sync(0xffffffffu, mm, o));
        const float thr = mm - 1.0f;     // valid lower bound on tau*

        // ---- gather candidates {x > thr} (rare for gaussian rows) ----
        {
            float vals[16] = {c0.x, c0.y, c0.z, c0.w, c1.x, c1.y, c1.z, c1.w,
                              c2.x, c2.y, c2.z, c2.w, c3.x, c3.y, c3.z, c3.w};
            #pragma unroll
            for (int i = 0; i < 16; i++) {
                if (vals[i] > thr) {
                    int p = atomicAdd(&s_cnt, 1);
                    if (p < BUF) sbuf[p] = vals[i];
                }
            }
        }
        __syncthreads();
        const int cnt = s_cnt;

        if (cnt <= BUF) {
            // ---- Michelot fixed-point on the tiny candidate set (warp 0) ----
            if (tid < 32) {
                float tau = thr;
                int prev = -1;
                for (int it = 0; it < cnt + 2; it++) {
                    float s = 0.0f; int k = 0;
                    for (int j = tid; j < cnt; j += 32) {
                        float v = sbuf[j];
                        if (v > tau) { s += v; k++; }
                    }
                    #pragma unroll
                    for (int o = 16; o > 0; o >>= 1) {
                        s += __shfl_xor_sync(0xffffffffu, s, o);
                        k += __shfl_xor_sync(0xffffffffu, k, o);
                    }
                    tau = (s - 1.0f) / (float)k;
                    if (k == prev) break;   // active set stable -> fixed point
                    prev = k;
                }
                if (tid == 0) s_tau = tau;
            }
            __syncthreads();
        } else {
            // ---- Fallback: block-wide Michelot over register values ----
            float tau = thr;
            int prev = -1;
            for (int it = 0; it < D + 2; it++) {
                float s = 0.0f; int k = 0;
                float vals[16] = {c0.x, c0.y, c0.z, c0.w, c1.x, c1.y, c1.z, c1.w,
                                  c2.x, c2.y, c2.z, c2.w, c3.x, c3.y, c3.z, c3.w};
                #pragma unroll
                for (int i = 0; i < 16; i++)
                    if (vals[i] > tau) { s += vals[i]; k++; }
                #pragma unroll
                for (int o = 16; o > 0; o >>= 1) {
                    s += __shfl_xor_sync(0xffffffffu, s, o);
                    k += __shfl_xor_sync(0xffffffffu, k, o);
                }
                if (lid == 0) { sredf[tid >> 5] = s; sredk[tid >> 5] = k; }
                __syncthreads();
                if (tid == 0) {
                    float S = 0.0f; int K = 0;
                    #pragma unroll
                    for (int w = 0; w < NWARPS; w++) { S += sredf[w]; K += sredk[w]; }
                    s_tau = (S - 1.0f) / (float)K;
                    s_k = K;
                }
                __syncthreads();
                tau = s_tau;
                int K = s_k;
                if (K == prev) break;
                prev = K;
            }
            __syncthreads();
        }

        if (tid == 0) s_cnt = 0;   // next gather is >=2 barriers away

        // ---- write relu(x - tau) from registers (streaming stores) ----
        const float tau = s_tau;
        c0.x = fmaxf(c0.x - tau, 0.0f); c0.y = fmaxf(c0.y - tau, 0.0f);
        c0.z = fmaxf(c0.z - tau, 0.0f); c0.w = fmaxf(c0.w - tau, 0.0f);
        c1.x = fmaxf(c1.x - tau, 0.0f); c1.y = fmaxf(c1.y - tau, 0.0f);
        c1.z = fmaxf(c1.z - tau, 0.0f); c1.w = fmaxf(c1.w - tau, 0.0f);
        c2.x = fmaxf(c2.x - tau, 0.0f); c2.y = fmaxf(c2.y - tau, 0.0f);
        c2.z = fmaxf(c2.z - tau, 0.0f); c2.w = fmaxf(c2.w - tau, 0.0f);
        c3.x = fmaxf(c3.x - tau, 0.0f); c3.y = fmaxf(c3.y - tau, 0.0f);
        c3.z = fmaxf(c3.z - tau, 0.0f); c3.w = fmaxf(c3.w - tau, 0.0f);
        float4* __restrict__ xout = reinterpret_cast<float4*>(out + (size_t)r * D);
        __stcs(&xout[tid],               c0);
        __stcs(&xout[tid + THREADS],     c1);
        __stcs(&xout[tid + 2 * THREADS], c2);
        __stcs(&xout[tid + 3 * THREADS], c3);

        if (!has_next) break;
        cur ^= 1;
        r = rn;
    }
}

extern "C" void kernel_launch(void* const* d_in, const int* in_sizes, int n_in,
                              void* d_out, int out_size) {
    const float* x = (const float*)d_in[0];
    float* out = (float*)d_out;
    const int rows = in_sizes[0] / D;   // 8192

    const int dyn_smem = 2 * D * (int)sizeof(float);   // 64 KB double buffer
    cudaFuncSetAttribute(sparsemax_kernel,
                         cudaFuncAttributeMaxDynamicSharedMemorySize, dyn_smem);

    int dev = 0;
    cudaGetDevice(&dev);
    int nsm = 148;
    cudaDeviceGetAttribute(&nsm, cudaDevAttrMultiProcessorCount, dev);
    int grid = nsm * 3;                 // 3 CTAs/SM, persistent, TMA depth-1 + L2 prefetch depth-2
    if (grid > rows) grid = rows;

    sparsemax_kernel<<<grid, THREADS, dyn_smem>>>(x, out, rows);
}